// round 1
// baseline (speedup 1.0000x reference)
#include <cuda_runtime.h>

#define NROWS 1000000
#define H     128
#define K     64
#define TEMP  30.0f

// Scratch accumulators (no device mallocs allowed).
__device__ float g_sums[K * H];
__device__ float g_cnts[K];

// ---------------------------------------------------------------------------
// k0: zero the global accumulators (graph replays must be deterministic)
// ---------------------------------------------------------------------------
__global__ void k_zero() {
    int i = blockIdx.x * blockDim.x + threadIdx.x;
    if (i < K * H) g_sums[i] = 0.0f;
    if (i < K)     g_cnts[i] = 0.0f;
}

// ---------------------------------------------------------------------------
// k1: row-wise L2 normalize z -> zn, and accumulate per-community sums/counts
//     Warp-per-row; block-local smem accumulator flushed via global atomics.
// ---------------------------------------------------------------------------
__global__ void __launch_bounds__(256)
k_norm_acc(const float* __restrict__ z, const int* __restrict__ comm,
           float* __restrict__ zn) {
    __shared__ float s_sum[K * H];
    __shared__ float s_cnt[K];

    int tid = threadIdx.x;
    for (int i = tid; i < K * H; i += blockDim.x) s_sum[i] = 0.0f;
    if (tid < K) s_cnt[tid] = 0.0f;
    __syncthreads();

    int lane   = tid & 31;
    int warp   = tid >> 5;
    int nwarps = blockDim.x >> 5;

    for (long row = (long)blockIdx.x * nwarps + warp; row < NROWS;
         row += (long)gridDim.x * nwarps) {
        const float* zr = z + row * (long)H;
        float v0 = zr[lane];
        float v1 = zr[lane + 32];
        float v2 = zr[lane + 64];
        float v3 = zr[lane + 96];
        float ss = v0 * v0 + v1 * v1 + v2 * v2 + v3 * v3;
        #pragma unroll
        for (int o = 16; o; o >>= 1) ss += __shfl_xor_sync(0xffffffffu, ss, o);
        float inv = rsqrtf(ss);
        v0 *= inv; v1 *= inv; v2 *= inv; v3 *= inv;

        float* znr = zn + row * (long)H;
        znr[lane]      = v0;
        znr[lane + 32] = v1;
        znr[lane + 64] = v2;
        znr[lane + 96] = v3;

        int c = comm[row];
        float* sb = s_sum + c * H;
        atomicAdd(sb + lane,      v0);   // lanes hit distinct banks -> spread ATOMS
        atomicAdd(sb + lane + 32, v1);
        atomicAdd(sb + lane + 64, v2);
        atomicAdd(sb + lane + 96, v3);
        if (lane == 0) atomicAdd(&s_cnt[c], 1.0f);
    }
    __syncthreads();

    for (int i = tid; i < K * H; i += blockDim.x) {
        float v = s_sum[i];
        if (v != 0.0f) atomicAdd(&g_sums[i], v);
        else           atomicAdd(&g_sums[i], v);  // keep deterministic op count
    }
    if (tid < K) atomicAdd(&g_cnts[tid], s_cnt[tid]);
}

// ---------------------------------------------------------------------------
// k2: mu = sums / counts
// ---------------------------------------------------------------------------
__global__ void k_mu(float* __restrict__ mu) {
    int i = blockIdx.x * blockDim.x + threadIdx.x;
    if (i < K * H) {
        float c = g_cnts[i / H];
        mu[i] = g_sums[i] / fmaxf(c, 1.0f);
    }
}

// ---------------------------------------------------------------------------
// k3: dist = zn @ mu^T  (per-row, mu broadcast from smem), softmax -> r
//     Thread-per-row: all lanes of a warp iterate (k, h) in lockstep so LDS of
//     mu is a same-address broadcast (conflict-free). FMA-pipe bound.
// ---------------------------------------------------------------------------
__global__ void __launch_bounds__(256)
k_dist_softmax(const float* __restrict__ zn, const float* __restrict__ mu,
               float* __restrict__ r, float* __restrict__ dist) {
    __shared__ float s_mu[K * H];
    int tid = threadIdx.x;
    for (int i = tid; i < K * H; i += blockDim.x) s_mu[i] = mu[i];
    __syncthreads();

    for (long row = (long)blockIdx.x * blockDim.x + tid; row < NROWS;
         row += (long)gridDim.x * blockDim.x) {
        float acc[K];
        #pragma unroll
        for (int k = 0; k < K; k++) acc[k] = 0.0f;

        const float4* zr = (const float4*)(zn + row * (long)H);
        for (int hc = 0; hc < H / 4; hc++) {
            float4 zv = zr[hc];
            #pragma unroll
            for (int k = 0; k < K; k++) {
                float4 m = ((const float4*)(s_mu + k * H))[hc];
                acc[k] += zv.x * m.x;
                acc[k] += zv.y * m.y;
                acc[k] += zv.z * m.z;
                acc[k] += zv.w * m.w;
            }
        }

        // write dist row (vectorized)
        float4* dr = (float4*)(dist + row * (long)K);
        #pragma unroll
        for (int kc = 0; kc < K / 4; kc++)
            dr[kc] = make_float4(acc[4 * kc], acc[4 * kc + 1],
                                 acc[4 * kc + 2], acc[4 * kc + 3]);

        // softmax over K with max-subtraction
        float mx = acc[0];
        #pragma unroll
        for (int k = 1; k < K; k++) mx = fmaxf(mx, acc[k]);
        float sum = 0.0f;
        #pragma unroll
        for (int k = 0; k < K; k++) {
            acc[k] = __expf(TEMP * (acc[k] - mx));
            sum += acc[k];
        }
        float is = 1.0f / sum;

        float4* rr = (float4*)(r + row * (long)K);
        #pragma unroll
        for (int kc = 0; kc < K / 4; kc++)
            rr[kc] = make_float4(acc[4 * kc] * is, acc[4 * kc + 1] * is,
                                 acc[4 * kc + 2] * is, acc[4 * kc + 3] * is);
    }
}

// ---------------------------------------------------------------------------
// kernel_launch: out layout = zn [N*H] | mu [K*H] | r [N*K] | dist [N*K]
// ---------------------------------------------------------------------------
extern "C" void kernel_launch(void* const* d_in, const int* in_sizes, int n_in,
                              void* d_out, int out_size) {
    const float* z    = (const float*)d_in[0];
    const int*   comm = (const int*)d_in[1];

    float* out  = (float*)d_out;
    float* zn   = out;
    float* mu   = zn + (long)NROWS * H;
    float* rr   = mu + (long)K * H;
    float* dist = rr + (long)NROWS * K;

    k_zero<<<(K * H + 255) / 256, 256>>>();
    k_norm_acc<<<592, 256>>>(z, comm, zn);
    k_mu<<<(K * H + 255) / 256, 256>>>(mu);
    k_dist_softmax<<<592, 256>>>(zn, mu, rr, dist);
}

// round 2
// speedup vs baseline: 1.2875x; 1.2875x over previous
#include <cuda_runtime.h>

#define NROWS 1000000
#define H     128
#define K     64
#define TEMP  30.0f
#define MTILE 128          // rows per block in k3
#define ZSTRF 132          // zn_s row stride in floats (pad: 4-float multiple)

typedef unsigned long long u64;

// Packed fp32x2 FMA (Blackwell): d = a*b + c elementwise on 2 floats.
__device__ __forceinline__ u64 ffma2(u64 a, u64 b, u64 c) {
    u64 d;
    asm("fma.rn.f32x2 %0, %1, %2, %3;" : "=l"(d) : "l"(a), "l"(b), "l"(c));
    return d;
}
__device__ __forceinline__ float hsum2(u64 v) {
    float x, y;
    asm("mov.b64 {%0, %1}, %2;" : "=f"(x), "=f"(y) : "l"(v));
    return x + y;
}

// Scratch accumulators (no device mallocs allowed).
__device__ float g_sums[K * H];
__device__ float g_cnts[K];

// ---------------------------------------------------------------------------
// k0: zero the global accumulators (graph replays must be deterministic)
// ---------------------------------------------------------------------------
__global__ void k_zero() {
    int i = blockIdx.x * blockDim.x + threadIdx.x;
    if (i < K * H) g_sums[i] = 0.0f;
    if (i < K)     g_cnts[i] = 0.0f;
}

// ---------------------------------------------------------------------------
// k1: row-wise L2 normalize z -> zn, accumulate per-community sums/counts.
// ---------------------------------------------------------------------------
__global__ void __launch_bounds__(256)
k_norm_acc(const float* __restrict__ z, const int* __restrict__ comm,
           float* __restrict__ zn) {
    __shared__ float s_sum[K * H];
    __shared__ float s_cnt[K];

    int tid = threadIdx.x;
    for (int i = tid; i < K * H; i += blockDim.x) s_sum[i] = 0.0f;
    if (tid < K) s_cnt[tid] = 0.0f;
    __syncthreads();

    int lane   = tid & 31;
    int warp   = tid >> 5;
    int nwarps = blockDim.x >> 5;

    for (long row = (long)blockIdx.x * nwarps + warp; row < NROWS;
         row += (long)gridDim.x * nwarps) {
        const float* zr = z + row * (long)H;
        float v0 = zr[lane];
        float v1 = zr[lane + 32];
        float v2 = zr[lane + 64];
        float v3 = zr[lane + 96];
        float ss = v0 * v0 + v1 * v1 + v2 * v2 + v3 * v3;
        #pragma unroll
        for (int o = 16; o; o >>= 1) ss += __shfl_xor_sync(0xffffffffu, ss, o);
        float inv = rsqrtf(ss);
        v0 *= inv; v1 *= inv; v2 *= inv; v3 *= inv;

        float* znr = zn + row * (long)H;
        znr[lane]      = v0;
        znr[lane + 32] = v1;
        znr[lane + 64] = v2;
        znr[lane + 96] = v3;

        int c = comm[row];
        float* sb = s_sum + c * H;
        atomicAdd(sb + lane,      v0);
        atomicAdd(sb + lane + 32, v1);
        atomicAdd(sb + lane + 64, v2);
        atomicAdd(sb + lane + 96, v3);
        if (lane == 0) atomicAdd(&s_cnt[c], 1.0f);
    }
    __syncthreads();

    for (int i = tid; i < K * H; i += blockDim.x)
        atomicAdd(&g_sums[i], s_sum[i]);
    if (tid < K) atomicAdd(&g_cnts[tid], s_cnt[tid]);
}

// ---------------------------------------------------------------------------
// k2: mu = sums / counts
// ---------------------------------------------------------------------------
__global__ void k_mu(float* __restrict__ mu) {
    int i = blockIdx.x * blockDim.x + threadIdx.x;
    if (i < K * H) {
        float c = g_cnts[i / H];
        mu[i] = g_sums[i] / fmaxf(c, 1.0f);
    }
}

// ---------------------------------------------------------------------------
// k3: register-tiled GEMM dist = zn @ mu^T + fused softmax -> r
//   Block = 256 threads = 32 (m) x 8 (kk). Thread owns rows 4m..4m+3 and
//   k-cols {4kk..4kk+3} U {32+4kk..35+4kk}. Accumulators are packed f32x2
//   (even-h, odd-h) partials, combined at the end. mu tile is XOR-swizzled
//   at 16B granularity so the 8 kk-lanes of each LDS.128 phase are
//   conflict-free; zn LDS.128 phases are pure broadcast by construction.
// ---------------------------------------------------------------------------
extern __shared__ float k3_smem[];

__global__ void __launch_bounds__(256, 2)
k_dist_softmax(const float* __restrict__ zn, const float* __restrict__ mu,
               float* __restrict__ r, float* __restrict__ dist) {
    float* zn_s = k3_smem;                 // MTILE * ZSTRF floats
    float* mu_s = k3_smem + MTILE * ZSTRF; // K * H floats (swizzled)

    int tid  = threadIdx.x;
    long base = (long)blockIdx.x * MTILE;

    // Load mu (K*H = 8192 floats) with 16B-granular XOR swizzle on h-slot.
    {
        const float4* mug  = (const float4*)mu;
        float4*       mus4 = (float4*)mu_s;
        #pragma unroll
        for (int i = 0; i < (K * H / 4) / 256; i++) {   // 8 iters
            int v  = i * 256 + tid;
            int k  = v >> 5;        // mu row
            int hc = v & 31;        // float4 slot within row
            mus4[k * 32 + (hc ^ ((k >> 2) & 7))] = mug[v];
        }
    }
    // Load zn tile: 128 rows x 128 h, coalesced gmem, padded smem rows.
    {
        const float4* zng = (const float4*)zn;
        #pragma unroll
        for (int i = 0; i < (MTILE * 32) / 256; i++) {  // 16 iters
            int v   = i * 256 + tid;
            int row = v >> 5;
            int hc  = v & 31;
            float4 val = make_float4(0.f, 0.f, 0.f, 0.f);
            if (base + row < NROWS) val = zng[(base + row) * 32 + hc];
            *(float4*)(zn_s + row * ZSTRF + hc * 4) = val;
        }
    }
    __syncthreads();

    int m  = tid >> 3;   // 0..31
    int kk = tid & 7;    // 0..7
    int r0 = 4 * m;      // local row base

    u64 acc[4][8];
    #pragma unroll
    for (int i = 0; i < 4; i++)
        #pragma unroll
        for (int q = 0; q < 8; q++) acc[i][q] = 0ull;

    #pragma unroll 2
    for (int hc = 0; hc < 32; hc++) {
        ulonglong2 z2[4];
        #pragma unroll
        for (int i = 0; i < 4; i++)
            z2[i] = *(const ulonglong2*)(zn_s + (r0 + i) * ZSTRF + hc * 4);

        #pragma unroll
        for (int q = 0; q < 8; q++) {
            int k = (q < 4) ? (4 * kk + q) : (32 + 4 * kk + (q - 4));
            // swizzle slot: (k>>2)&7 == kk for both k-groups
            ulonglong2 m2 = *(const ulonglong2*)(mu_s + k * H + ((hc ^ kk) * 4));
            #pragma unroll
            for (int i = 0; i < 4; i++) {
                acc[i][q] = ffma2(z2[i].x, m2.x, acc[i][q]);
                acc[i][q] = ffma2(z2[i].y, m2.y, acc[i][q]);
            }
        }
    }

    // Horizontal combine (even-h + odd-h partials)
    float v[4][8];
    #pragma unroll
    for (int i = 0; i < 4; i++)
        #pragma unroll
        for (int q = 0; q < 8; q++) v[i][q] = hsum2(acc[i][q]);

    // Per-row softmax across the 8 kk-lanes (lane = (m%4)*8 + kk).
    #pragma unroll
    for (int i = 0; i < 4; i++) {
        long row = base + r0 + i;
        bool valid = row < NROWS;

        float mx = v[i][0];
        #pragma unroll
        for (int q = 1; q < 8; q++) mx = fmaxf(mx, v[i][q]);
        #pragma unroll
        for (int o = 4; o; o >>= 1)
            mx = fmaxf(mx, __shfl_xor_sync(0xffffffffu, mx, o));

        float e[8], sum = 0.f;
        #pragma unroll
        for (int q = 0; q < 8; q++) {
            e[q] = __expf(TEMP * (v[i][q] - mx));
            sum += e[q];
        }
        #pragma unroll
        for (int o = 4; o; o >>= 1)
            sum += __shfl_xor_sync(0xffffffffu, sum, o);
        float is = 1.0f / sum;

        if (valid) {
            float* dr = dist + row * (long)K;
            float* rr = r    + row * (long)K;
            *(float4*)(dr + 4 * kk)      = make_float4(v[i][0], v[i][1], v[i][2], v[i][3]);
            *(float4*)(dr + 32 + 4 * kk) = make_float4(v[i][4], v[i][5], v[i][6], v[i][7]);
            *(float4*)(rr + 4 * kk)      = make_float4(e[0] * is, e[1] * is, e[2] * is, e[3] * is);
            *(float4*)(rr + 32 + 4 * kk) = make_float4(e[4] * is, e[5] * is, e[6] * is, e[7] * is);
        }
    }
}

// ---------------------------------------------------------------------------
// kernel_launch: out layout = zn [N*H] | mu [K*H] | r [N*K] | dist [N*K]
// ---------------------------------------------------------------------------
extern "C" void kernel_launch(void* const* d_in, const int* in_sizes, int n_in,
                              void* d_out, int out_size) {
    const float* z    = (const float*)d_in[0];
    const int*   comm = (const int*)d_in[1];

    float* out  = (float*)d_out;
    float* zn   = out;
    float* mu   = zn + (long)NROWS * H;
    float* rr   = mu + (long)K * H;
    float* dist = rr + (long)NROWS * K;

    const int k3_smem_bytes = (MTILE * ZSTRF + K * H) * sizeof(float); // 100352
    static bool attr_set = false;
    if (!attr_set) {
        cudaFuncSetAttribute(k_dist_softmax,
                             cudaFuncAttributeMaxDynamicSharedMemorySize,
                             k3_smem_bytes);
        attr_set = true;
    }

    k_zero<<<(K * H + 255) / 256, 256>>>();
    k_norm_acc<<<592, 256>>>(z, comm, zn);
    k_mu<<<(K * H + 255) / 256, 256>>>(mu);

    int nblk = (NROWS + MTILE - 1) / MTILE;  // 7813
    k_dist_softmax<<<nblk, 256, k3_smem_bytes>>>(zn, mu, rr, dist);
}